// round 1
// baseline (speedup 1.0000x reference)
#include <cuda_runtime.h>
#include <cstdint>

#define N_NODES 100000
#define N_EDGES 1600000
#define N_GRAPHS 256
#define IN_C 64
#define HID 128
#define BN_EPS 1e-5f

// ---------------- scratch (device globals; no allocation) ----------------
__device__ float g_H[(size_t)N_NODES * HID];     // post-activation features
__device__ float g_AGG[(size_t)N_NODES * HID];   // h + sum aggregation (GEMM input)
__device__ float g_Z[(size_t)N_NODES * HID];     // pre-BN MLP output
__device__ float g_STATS[2 * HID];               // column sum / sumsq
__device__ float g_SCALE[HID];
__device__ float g_SHIFT[HID];
__device__ float g_POOL[N_GRAPHS * HID];
__device__ float g_CINV[N_GRAPHS];

// ---------------- small utility kernels ----------------
__global__ void zero_kernel(float* p, int n) {
    int i = blockIdx.x * blockDim.x + threadIdx.x;
    if (i < n) p[i] = 0.f;
}

__global__ void copy4_kernel(float4* dst, const float4* __restrict__ src, int n4) {
    int i = blockIdx.x * blockDim.x + threadIdx.x;
    if (i < n4) dst[i] = src[i];
}

// ---------------- scatter: agg[dst] += h[src] (vector red) ----------------
template <int C>
__global__ void scatter_kernel(const int* __restrict__ ei,
                               const float* __restrict__ h,
                               float* __restrict__ agg) {
    const int CH = C / 4;
    long long idx = (long long)blockIdx.x * blockDim.x + threadIdx.x;
    if (idx >= (long long)N_EDGES * CH) return;
    int e = (int)(idx / CH);
    int c = ((int)idx % CH) * 4;
    int s = ei[e];
    int d = ei[N_EDGES + e];
    float4 v = *(const float4*)(h + (long long)s * C + c);
    float* p = agg + (long long)d * C + c;
    asm volatile("red.global.add.v4.f32 [%0], {%1,%2,%3,%4};"
                 :: "l"(p), "f"(v.x), "f"(v.y), "f"(v.z), "f"(v.w) : "memory");
}

// ---------------- fused MLP: zout = relu(z@w1+b1)@w2+b2, + BN stats ----------------
// block: 256 threads, 64 rows per block. SMEM holds w1, w2, z-tile, hidden-tile.
template <int CIN>
__global__ __launch_bounds__(256, 1)
void mlp_kernel(const float* __restrict__ zin,
                const float* __restrict__ w1, const float* __restrict__ b1,
                const float* __restrict__ w2, const float* __restrict__ b2,
                float* __restrict__ zout, float* __restrict__ stats) {
    extern __shared__ float sm[];
    float* sw1  = sm;                      // CIN*HID
    float* sw2  = sw1 + CIN * HID;         // HID*HID
    float* sz   = sw2 + HID * HID;         // 64*(CIN+1)  (padded)
    float* sh   = sz + 64 * (CIN + 1);     // 64*(HID+1)  (padded)
    float* ssum = sh + 64 * (HID + 1);     // HID
    float* ssq  = ssum + HID;              // HID

    const int tid  = threadIdx.x;
    const int row0 = blockIdx.x * 64;

    // weights -> smem (float4)
    for (int i = tid; i < CIN * HID / 4; i += 256) ((float4*)sw1)[i] = ((const float4*)w1)[i];
    for (int i = tid; i < HID * HID / 4; i += 256) ((float4*)sw2)[i] = ((const float4*)w2)[i];
    if (tid < HID) { ssum[tid] = 0.f; ssq[tid] = 0.f; }

    // z tile -> smem (padded rows), zero-fill out-of-range rows
    for (int i = tid; i < 64 * CIN; i += 256) {
        int r = i / CIN, c = i % CIN;
        int gr = row0 + r;
        sz[r * (CIN + 1) + c] = (gr < N_NODES) ? zin[(long long)gr * CIN + c] : 0.f;
    }
    __syncthreads();

    const int tx = tid & 15, ty = tid >> 4;
    const int nbase = tx * 8;

    // ---- GEMM1: hidden = relu(z @ w1 + b1) ----
    float acc[4][8];
    #pragma unroll
    for (int i = 0; i < 4; i++)
        #pragma unroll
        for (int j = 0; j < 8; j++) acc[i][j] = b1[nbase + j];

    #pragma unroll 4
    for (int k = 0; k < CIN; k++) {
        float zr[4];
        #pragma unroll
        for (int i = 0; i < 4; i++) zr[i] = sz[(ty + 16 * i) * (CIN + 1) + k];
        float4 wa = *(const float4*)&sw1[k * HID + nbase];
        float4 wb = *(const float4*)&sw1[k * HID + nbase + 4];
        float wv[8] = {wa.x, wa.y, wa.z, wa.w, wb.x, wb.y, wb.z, wb.w};
        #pragma unroll
        for (int i = 0; i < 4; i++)
            #pragma unroll
            for (int j = 0; j < 8; j++) acc[i][j] = fmaf(zr[i], wv[j], acc[i][j]);
    }
    #pragma unroll
    for (int i = 0; i < 4; i++)
        #pragma unroll
        for (int j = 0; j < 8; j++)
            sh[(ty + 16 * i) * (HID + 1) + nbase + j] = fmaxf(acc[i][j], 0.f);
    __syncthreads();

    // ---- GEMM2: out = hidden @ w2 + b2 ----
    float acc2[4][8];
    #pragma unroll
    for (int i = 0; i < 4; i++)
        #pragma unroll
        for (int j = 0; j < 8; j++) acc2[i][j] = b2[nbase + j];

    #pragma unroll 4
    for (int k = 0; k < HID; k++) {
        float hr[4];
        #pragma unroll
        for (int i = 0; i < 4; i++) hr[i] = sh[(ty + 16 * i) * (HID + 1) + k];
        float4 wa = *(const float4*)&sw2[k * HID + nbase];
        float4 wb = *(const float4*)&sw2[k * HID + nbase + 4];
        float wv[8] = {wa.x, wa.y, wa.z, wa.w, wb.x, wb.y, wb.z, wb.w};
        #pragma unroll
        for (int i = 0; i < 4; i++)
            #pragma unroll
            for (int j = 0; j < 8; j++) acc2[i][j] = fmaf(hr[i], wv[j], acc2[i][j]);
    }

    // ---- epilogue: store pre-BN z, accumulate column stats ----
    float s[8], q[8];
    #pragma unroll
    for (int j = 0; j < 8; j++) { s[j] = 0.f; q[j] = 0.f; }

    #pragma unroll
    for (int i = 0; i < 4; i++) {
        int gr = row0 + ty + 16 * i;
        if (gr < N_NODES) {
            float4 o0 = make_float4(acc2[i][0], acc2[i][1], acc2[i][2], acc2[i][3]);
            float4 o1 = make_float4(acc2[i][4], acc2[i][5], acc2[i][6], acc2[i][7]);
            *(float4*)&zout[(long long)gr * HID + nbase]     = o0;
            *(float4*)&zout[(long long)gr * HID + nbase + 4] = o1;
            #pragma unroll
            for (int j = 0; j < 8; j++) {
                float v = acc2[i][j];
                s[j] += v; q[j] += v * v;
            }
        }
    }
    #pragma unroll
    for (int j = 0; j < 8; j++) {
        atomicAdd(&ssum[nbase + j], s[j]);
        atomicAdd(&ssq[nbase + j], q[j]);
    }
    __syncthreads();
    if (tid < HID) {
        atomicAdd(&stats[tid], ssum[tid]);
        atomicAdd(&stats[HID + tid], ssq[tid]);
    }
}

// ---------------- BN finalize: scale/shift from accumulated stats ----------------
__global__ void bn_finalize_kernel(const float* __restrict__ gamma,
                                   const float* __restrict__ beta,
                                   const float* __restrict__ stats,
                                   float* __restrict__ scale,
                                   float* __restrict__ shift) {
    int c = threadIdx.x;
    float mean = stats[c] * (1.f / N_NODES);
    float var  = stats[HID + c] * (1.f / N_NODES) - mean * mean;
    float inv  = rsqrtf(var + BN_EPS);
    float sc   = gamma[c] * inv;
    scale[c] = sc;
    shift[c] = beta[c] - mean * sc;
}

// ---------------- BN apply + relu; optional copy into agg buffer ----------------
__global__ void bn_apply_kernel(const float4* __restrict__ z, float4* __restrict__ h,
                                float4* __restrict__ agg, int writeAgg,
                                const float* __restrict__ scale,
                                const float* __restrict__ shift) {
    int idx = blockIdx.x * blockDim.x + threadIdx.x;
    if (idx >= N_NODES * HID / 4) return;
    int c4 = (idx & 31) * 4;
    float4 v = z[idx];
    v.x = fmaxf(fmaf(v.x, scale[c4 + 0], shift[c4 + 0]), 0.f);
    v.y = fmaxf(fmaf(v.y, scale[c4 + 1], shift[c4 + 1]), 0.f);
    v.z = fmaxf(fmaf(v.z, scale[c4 + 2], shift[c4 + 2]), 0.f);
    v.w = fmaxf(fmaf(v.w, scale[c4 + 3], shift[c4 + 3]), 0.f);
    h[idx] = v;
    if (writeAgg) agg[idx] = v;
}

// ---------------- mean pool (batch is sorted: run-length local accumulate) ----------------
__global__ void pool_kernel(const float* __restrict__ h, const int* __restrict__ batch,
                            float* __restrict__ pool) {
    __shared__ int sb[256];
    int r0  = blockIdx.x * 256;
    int tid = threadIdx.x;  // 128 threads = one column each
    for (int i = tid; i < 256; i += 128) {
        int gr = r0 + i;
        sb[i] = (gr < N_NODES) ? batch[gr] : -1;
    }
    __syncthreads();
    int c = tid;
    float sum = 0.f;
    int cur = sb[0];
    for (int i = 0; i < 256; i++) {
        int gr = r0 + i;
        if (gr >= N_NODES) break;
        int b = sb[i];
        if (b != cur) {
            atomicAdd(&pool[cur * HID + c], sum);
            sum = 0.f; cur = b;
        }
        sum += h[(long long)gr * HID + c];
    }
    if (cur >= 0) atomicAdd(&pool[cur * HID + c], sum);
}

// ---------------- per-graph counts via binary search (batch sorted) ----------------
__global__ void count_kernel(const int* __restrict__ batch, float* __restrict__ cinv) {
    int g = threadIdx.x;  // 256 threads
    int lo = 0, hi = N_NODES;
    while (lo < hi) { int m = (lo + hi) >> 1; if (batch[m] < g) lo = m + 1; else hi = m; }
    int a = lo;
    lo = 0; hi = N_NODES;
    while (lo < hi) { int m = (lo + hi) >> 1; if (batch[m] < g + 1) lo = m + 1; else hi = m; }
    float cnt = (float)(lo - a);
    cinv[g] = 1.f / fmaxf(cnt, 1.f);
}

// ---------------- final projection: out[g] = (pool[g]*cinv) @ W + b ----------------
__global__ void proj_kernel(const float* __restrict__ w, const float* __restrict__ b,
                            const float* __restrict__ pool, const float* __restrict__ cinv,
                            float* __restrict__ out) {
    __shared__ float hg[HID];
    int g = blockIdx.x, t = threadIdx.x;  // 128 threads
    hg[t] = pool[g * HID + t] * cinv[g];
    __syncthreads();
    float acc = b[t];
    #pragma unroll 8
    for (int k = 0; k < HID; k++) acc = fmaf(hg[k], w[k * HID + t], acc);
    out[g * HID + t] = acc;
}

// ---------------- host orchestration ----------------
static void* sym(const void* s) {
    void* p = nullptr;
    cudaGetSymbolAddress(&p, s);
    return p;
}

extern "C" void kernel_launch(void* const* d_in, const int* in_sizes, int n_in,
                              void* d_out, int out_size) {
    const float* x     = (const float*)d_in[0];
    const int*   ei    = (const int*)d_in[1];
    const int*   batch = (const int*)d_in[2];
    const float* L[3][6];
    for (int l = 0; l < 3; l++)
        for (int k = 0; k < 6; k++) L[l][k] = (const float*)d_in[3 + 6 * l + k];
    const float* proj_w = (const float*)d_in[21];
    const float* proj_b = (const float*)d_in[22];
    float* out = (float*)d_out;

    float* H     = (float*)sym(g_H);
    float* AGG   = (float*)sym(g_AGG);
    float* Z     = (float*)sym(g_Z);
    float* STATS = (float*)sym(g_STATS);
    float* SCALE = (float*)sym(g_SCALE);
    float* SHIFT = (float*)sym(g_SHIFT);
    float* POOL  = (float*)sym(g_POOL);
    float* CINV  = (float*)sym(g_CINV);

    const int smem64  = (IN_C * HID + HID * HID + 64 * (IN_C + 1) + 64 * (HID + 1) + 2 * HID) * 4;
    const int smem128 = (HID * HID + HID * HID + 64 * (HID + 1) + 64 * (HID + 1) + 2 * HID) * 4;
    cudaFuncSetAttribute(mlp_kernel<IN_C>, cudaFuncAttributeMaxDynamicSharedMemorySize, smem64);
    cudaFuncSetAttribute(mlp_kernel<HID>,  cudaFuncAttributeMaxDynamicSharedMemorySize, smem128);

    const int mlpBlocks = (N_NODES + 63) / 64;
    const int applyN4   = N_NODES * HID / 4;

    // ---- layer 0 (CIN=64): AGG = x; AGG += scatter(x) ----
    {
        int n4 = N_NODES * IN_C / 4;
        copy4_kernel<<<(n4 + 255) / 256, 256>>>((float4*)AGG, (const float4*)x, n4);
        long long sthreads = (long long)N_EDGES * (IN_C / 4);
        scatter_kernel<IN_C><<<(int)((sthreads + 255) / 256), 256>>>(ei, x, AGG);
        zero_kernel<<<1, 256>>>(STATS, 2 * HID);
        mlp_kernel<IN_C><<<mlpBlocks, 256, smem64>>>(AGG, L[0][0], L[0][1], L[0][2], L[0][3], Z, STATS);
        bn_finalize_kernel<<<1, HID>>>(L[0][4], L[0][5], STATS, SCALE, SHIFT);
        bn_apply_kernel<<<(applyN4 + 255) / 256, 256>>>((const float4*)Z, (float4*)H, (float4*)AGG, 1, SCALE, SHIFT);
    }

    // ---- layers 1,2 (CIN=128) ----
    for (int l = 1; l < 3; l++) {
        long long sthreads = (long long)N_EDGES * (HID / 4);
        scatter_kernel<HID><<<(int)((sthreads + 255) / 256), 256>>>(ei, H, AGG);
        zero_kernel<<<1, 256>>>(STATS, 2 * HID);
        mlp_kernel<HID><<<mlpBlocks, 256, smem128>>>(AGG, L[l][0], L[l][1], L[l][2], L[l][3], Z, STATS);
        bn_finalize_kernel<<<1, HID>>>(L[l][4], L[l][5], STATS, SCALE, SHIFT);
        int writeAgg = (l < 2) ? 1 : 0;
        bn_apply_kernel<<<(applyN4 + 255) / 256, 256>>>((const float4*)Z, (float4*)H, (float4*)AGG, writeAgg, SCALE, SHIFT);
    }

    // ---- pool + projection ----
    zero_kernel<<<(N_GRAPHS * HID + 255) / 256, 256>>>(POOL, N_GRAPHS * HID);
    pool_kernel<<<(N_NODES + 255) / 256, 128>>>(H, batch, POOL);
    count_kernel<<<1, N_GRAPHS>>>(batch, CINV);
    proj_kernel<<<N_GRAPHS, HID>>>(proj_w, proj_b, POOL, CINV, out);
}

// round 2
// speedup vs baseline: 1.5349x; 1.5349x over previous
#include <cuda_runtime.h>
#include <cstdint>

#define N_NODES 100000
#define N_EDGES 1600000
#define N_GRAPHS 256
#define IN_C 64
#define HID 128
#define BN_EPS 1e-5f

// ---------------- scratch (device globals; no allocation) ----------------
__device__ float g_H[(size_t)N_NODES * HID];     // post-activation features
__device__ float g_AGG[(size_t)N_NODES * HID];   // h + sum aggregation (GEMM input)
__device__ float g_Z[(size_t)N_NODES * HID];     // pre-BN MLP output
__device__ float g_STATS[2 * HID];               // column sum / sumsq
__device__ float g_SCALE[HID];
__device__ float g_SHIFT[HID];
__device__ float g_POOL[N_GRAPHS * HID];
__device__ float g_CINV[N_GRAPHS];

// ---------------- small utility kernels ----------------
__global__ void zero_kernel(float* p, int n) {
    int i = blockIdx.x * blockDim.x + threadIdx.x;
    if (i < n) p[i] = 0.f;
}

__global__ void copy4_kernel(float4* dst, const float4* __restrict__ src, int n4) {
    int i = blockIdx.x * blockDim.x + threadIdx.x;
    if (i < n4) dst[i] = src[i];
}

// ---------------- scatter: agg[dst] += h[src] (vector red) ----------------
template <int C>
__global__ void scatter_kernel(const int* __restrict__ ei,
                               const float* __restrict__ h,
                               float* __restrict__ agg) {
    const int CH = C / 4;
    long long idx = (long long)blockIdx.x * blockDim.x + threadIdx.x;
    if (idx >= (long long)N_EDGES * CH) return;
    int e = (int)(idx / CH);
    int c = ((int)idx % CH) * 4;
    int s = ei[e];
    int d = ei[N_EDGES + e];
    float4 v = *(const float4*)(h + (long long)s * C + c);
    float* p = agg + (long long)d * C + c;
    asm volatile("red.global.add.v4.f32 [%0], {%1,%2,%3,%4};"
                 :: "l"(p), "f"(v.x), "f"(v.y), "f"(v.z), "f"(v.w) : "memory");
}

// ---------------- fused MLP: zout = relu(z@w1+b1)@w2+b2, + BN stats ----------------
// 128 rows x 128 cols per block, 256 threads, 8x8 register tiles.
// K streamed from global in 32-wide chunks (weights broadcast via L2).
// Thread (tx,ty): tx=tid%16 owns cols {tx*4..tx*4+3} U {64+tx*4..64+tx*4+3};
//                 ty=tid/16 owns rows {ty*8..ty*8+7}.
#define CK 32           // k-chunk
#define SZ_STR 36       // z-chunk row stride (floats), 144B (16B-aligned)
#define SH_STR 132      // hidden row stride (floats), 528B (16B-aligned)

template <int CIN>
__global__ __launch_bounds__(256, 2)
void mlp_kernel(const float* __restrict__ zin,
                const float* __restrict__ w1, const float* __restrict__ b1,
                const float* __restrict__ w2, const float* __restrict__ b2,
                float* __restrict__ zout, float* __restrict__ stats) {
    extern __shared__ float sm[];
    float* sz   = sm;                        // 128 * SZ_STR
    float* sh   = sz + 128 * SZ_STR;         // 128 * SH_STR
    float* sw   = sh + 128 * SH_STR;         // CK * 128 (weight chunk)
    float* ssum = sw + CK * HID;             // HID
    float* ssq  = ssum + HID;                // HID

    const int tid  = threadIdx.x;
    const int row0 = blockIdx.x * 128;
    const int tx = tid & 15, ty = tid >> 4;
    const int c0 = tx * 4;            // first col quad
    const int c1 = 64 + tx * 4;       // second col quad
    const int r0 = ty * 8;            // first of 8 rows

    if (tid < HID) { ssum[tid] = 0.f; ssq[tid] = 0.f; }

    float acc[8][8];

    // ======== GEMM1: hidden = relu(z @ w1 + b1) ========
    {
        #pragma unroll
        for (int i = 0; i < 8; i++) {
            #pragma unroll
            for (int j = 0; j < 4; j++) { acc[i][j] = b1[c0 + j]; acc[i][4 + j] = b1[c1 + j]; }
        }
        const int NKC = CIN / CK;
        for (int kc = 0; kc < NKC; kc++) {
            __syncthreads();   // previous chunk consumed (and ssum init visible)
            // stage z chunk: 128 rows x 32 k  (1024 float4)
            #pragma unroll
            for (int t = 0; t < 4; t++) {
                int i = tid + t * 256;
                int r = i >> 3, q = i & 7;
                int gr = row0 + r;
                float4 v = make_float4(0.f, 0.f, 0.f, 0.f);
                if (gr < N_NODES)
                    v = *(const float4*)(zin + (size_t)gr * CIN + kc * CK + q * 4);
                *(float4*)&sz[r * SZ_STR + q * 4] = v;
            }
            // stage w1 chunk: 32 x 128 (1024 float4), contiguous
            #pragma unroll
            for (int t = 0; t < 4; t++) {
                int i = tid + t * 256;
                ((float4*)sw)[i] = ((const float4*)w1)[kc * (CK * HID / 4) + i];
            }
            __syncthreads();
            #pragma unroll 4
            for (int k = 0; k < CK; k++) {
                float zr[8];
                #pragma unroll
                for (int i = 0; i < 8; i++) zr[i] = sz[(r0 + i) * SZ_STR + k];
                float4 wa = *(const float4*)&sw[k * HID + c0];
                float4 wb = *(const float4*)&sw[k * HID + c1];
                #pragma unroll
                for (int i = 0; i < 8; i++) {
                    float z = zr[i];
                    acc[i][0] = fmaf(z, wa.x, acc[i][0]);
                    acc[i][1] = fmaf(z, wa.y, acc[i][1]);
                    acc[i][2] = fmaf(z, wa.z, acc[i][2]);
                    acc[i][3] = fmaf(z, wa.w, acc[i][3]);
                    acc[i][4] = fmaf(z, wb.x, acc[i][4]);
                    acc[i][5] = fmaf(z, wb.y, acc[i][5]);
                    acc[i][6] = fmaf(z, wb.z, acc[i][6]);
                    acc[i][7] = fmaf(z, wb.w, acc[i][7]);
                }
            }
        }
        // relu + store hidden tile (row-major, vector stores, conflict-free)
        #pragma unroll
        for (int i = 0; i < 8; i++) {
            float4 h0 = make_float4(fmaxf(acc[i][0], 0.f), fmaxf(acc[i][1], 0.f),
                                    fmaxf(acc[i][2], 0.f), fmaxf(acc[i][3], 0.f));
            float4 h1 = make_float4(fmaxf(acc[i][4], 0.f), fmaxf(acc[i][5], 0.f),
                                    fmaxf(acc[i][6], 0.f), fmaxf(acc[i][7], 0.f));
            *(float4*)&sh[(r0 + i) * SH_STR + c0] = h0;
            *(float4*)&sh[(r0 + i) * SH_STR + c1] = h1;
        }
    }

    // ======== GEMM2: out = hidden @ w2 + b2 ========
    {
        #pragma unroll
        for (int i = 0; i < 8; i++) {
            #pragma unroll
            for (int j = 0; j < 4; j++) { acc[i][j] = b2[c0 + j]; acc[i][4 + j] = b2[c1 + j]; }
        }
        for (int kc = 0; kc < HID / CK; kc++) {
            __syncthreads();   // sh writes done (kc=0) / prev w2 chunk consumed
            #pragma unroll
            for (int t = 0; t < 4; t++) {
                int i = tid + t * 256;
                ((float4*)sw)[i] = ((const float4*)w2)[kc * (CK * HID / 4) + i];
            }
            __syncthreads();
            #pragma unroll 4
            for (int k = 0; k < CK; k++) {
                int kk = kc * CK + k;
                float hr[8];
                #pragma unroll
                for (int i = 0; i < 8; i++) hr[i] = sh[(r0 + i) * SH_STR + kk];
                float4 wa = *(const float4*)&sw[k * HID + c0];
                float4 wb = *(const float4*)&sw[k * HID + c1];
                #pragma unroll
                for (int i = 0; i < 8; i++) {
                    float h = hr[i];
                    acc[i][0] = fmaf(h, wa.x, acc[i][0]);
                    acc[i][1] = fmaf(h, wa.y, acc[i][1]);
                    acc[i][2] = fmaf(h, wa.z, acc[i][2]);
                    acc[i][3] = fmaf(h, wa.w, acc[i][3]);
                    acc[i][4] = fmaf(h, wb.x, acc[i][4]);
                    acc[i][5] = fmaf(h, wb.y, acc[i][5]);
                    acc[i][6] = fmaf(h, wb.z, acc[i][6]);
                    acc[i][7] = fmaf(h, wb.w, acc[i][7]);
                }
            }
        }
    }

    // ======== epilogue: store pre-BN z, accumulate BN column stats ========
    float s[8], q[8];
    #pragma unroll
    for (int j = 0; j < 8; j++) { s[j] = 0.f; q[j] = 0.f; }

    #pragma unroll
    for (int i = 0; i < 8; i++) {
        int gr = row0 + r0 + i;
        if (gr < N_NODES) {
            float4 o0 = make_float4(acc[i][0], acc[i][1], acc[i][2], acc[i][3]);
            float4 o1 = make_float4(acc[i][4], acc[i][5], acc[i][6], acc[i][7]);
            *(float4*)&zout[(size_t)gr * HID + c0] = o0;
            *(float4*)&zout[(size_t)gr * HID + c1] = o1;
            #pragma unroll
            for (int j = 0; j < 8; j++) {
                float v = acc[i][j];
                s[j] += v; q[j] += v * v;
            }
        }
    }
    #pragma unroll
    for (int j = 0; j < 4; j++) {
        atomicAdd(&ssum[c0 + j], s[j]);
        atomicAdd(&ssq[c0 + j], q[j]);
        atomicAdd(&ssum[c1 + j], s[4 + j]);
        atomicAdd(&ssq[c1 + j], q[4 + j]);
    }
    __syncthreads();
    if (tid < HID) {
        atomicAdd(&stats[tid], ssum[tid]);
        atomicAdd(&stats[HID + tid], ssq[tid]);
    }
}

// ---------------- BN finalize: scale/shift from accumulated stats ----------------
__global__ void bn_finalize_kernel(const float* __restrict__ gamma,
                                   const float* __restrict__ beta,
                                   const float* __restrict__ stats,
                                   float* __restrict__ scale,
                                   float* __restrict__ shift) {
    int c = threadIdx.x;
    float mean = stats[c] * (1.f / N_NODES);
    float var  = stats[HID + c] * (1.f / N_NODES) - mean * mean;
    float inv  = rsqrtf(var + BN_EPS);
    float sc   = gamma[c] * inv;
    scale[c] = sc;
    shift[c] = beta[c] - mean * sc;
}

// ---------------- BN apply + relu; optional copy into agg buffer ----------------
__global__ void bn_apply_kernel(const float4* __restrict__ z, float4* __restrict__ h,
                                float4* __restrict__ agg, int writeAgg,
                                const float* __restrict__ scale,
                                const float* __restrict__ shift) {
    int idx = blockIdx.x * blockDim.x + threadIdx.x;
    if (idx >= N_NODES * HID / 4) return;
    int c4 = (idx & 31) * 4;
    float4 v = z[idx];
    v.x = fmaxf(fmaf(v.x, scale[c4 + 0], shift[c4 + 0]), 0.f);
    v.y = fmaxf(fmaf(v.y, scale[c4 + 1], shift[c4 + 1]), 0.f);
    v.z = fmaxf(fmaf(v.z, scale[c4 + 2], shift[c4 + 2]), 0.f);
    v.w = fmaxf(fmaf(v.w, scale[c4 + 3], shift[c4 + 3]), 0.f);
    h[idx] = v;
    if (writeAgg) agg[idx] = v;
}

// ---------------- mean pool (batch sorted: run-length local accumulate) ----------------
__global__ void pool_kernel(const float* __restrict__ h, const int* __restrict__ batch,
                            float* __restrict__ pool) {
    __shared__ int sb[256];
    int r0  = blockIdx.x * 256;
    int tid = threadIdx.x;  // 128 threads = one column each
    for (int i = tid; i < 256; i += 128) {
        int gr = r0 + i;
        sb[i] = (gr < N_NODES) ? batch[gr] : -1;
    }
    __syncthreads();
    int c = tid;
    float sum = 0.f;
    int cur = sb[0];
    for (int i = 0; i < 256; i++) {
        int gr = r0 + i;
        if (gr >= N_NODES) break;
        int b = sb[i];
        if (b != cur) {
            atomicAdd(&pool[cur * HID + c], sum);
            sum = 0.f; cur = b;
        }
        sum += h[(long long)gr * HID + c];
    }
    if (cur >= 0) atomicAdd(&pool[cur * HID + c], sum);
}

// ---------------- per-graph counts via binary search (batch sorted) ----------------
__global__ void count_kernel(const int* __restrict__ batch, float* __restrict__ cinv) {
    int g = threadIdx.x;  // 256 threads
    int lo = 0, hi = N_NODES;
    while (lo < hi) { int m = (lo + hi) >> 1; if (batch[m] < g) lo = m + 1; else hi = m; }
    int a = lo;
    lo = 0; hi = N_NODES;
    while (lo < hi) { int m = (lo + hi) >> 1; if (batch[m] < g + 1) lo = m + 1; else hi = m; }
    float cnt = (float)(lo - a);
    cinv[g] = 1.f / fmaxf(cnt, 1.f);
}

// ---------------- final projection: out[g] = (pool[g]*cinv) @ W + b ----------------
__global__ void proj_kernel(const float* __restrict__ w, const float* __restrict__ b,
                            const float* __restrict__ pool, const float* __restrict__ cinv,
                            float* __restrict__ out) {
    __shared__ float hg[HID];
    int g = blockIdx.x, t = threadIdx.x;  // 128 threads
    hg[t] = pool[g * HID + t] * cinv[g];
    __syncthreads();
    float acc = b[t];
    #pragma unroll 8
    for (int k = 0; k < HID; k++) acc = fmaf(hg[k], w[k * HID + t], acc);
    out[g * HID + t] = acc;
}

// ---------------- host orchestration ----------------
static void* sym(const void* s) {
    void* p = nullptr;
    cudaGetSymbolAddress(&p, s);
    return p;
}

extern "C" void kernel_launch(void* const* d_in, const int* in_sizes, int n_in,
                              void* d_out, int out_size) {
    const float* x     = (const float*)d_in[0];
    const int*   ei    = (const int*)d_in[1];
    const int*   batch = (const int*)d_in[2];
    const float* L[3][6];
    for (int l = 0; l < 3; l++)
        for (int k = 0; k < 6; k++) L[l][k] = (const float*)d_in[3 + 6 * l + k];
    const float* proj_w = (const float*)d_in[21];
    const float* proj_b = (const float*)d_in[22];
    float* out = (float*)d_out;

    float* H     = (float*)sym(g_H);
    float* AGG   = (float*)sym(g_AGG);
    float* Z     = (float*)sym(g_Z);
    float* STATS = (float*)sym(g_STATS);
    float* SCALE = (float*)sym(g_SCALE);
    float* SHIFT = (float*)sym(g_SHIFT);
    float* POOL  = (float*)sym(g_POOL);
    float* CINV  = (float*)sym(g_CINV);

    const int smemMlp = (128 * SZ_STR + 128 * SH_STR + CK * HID + 2 * HID) * 4;
    cudaFuncSetAttribute(mlp_kernel<IN_C>, cudaFuncAttributeMaxDynamicSharedMemorySize, smemMlp);
    cudaFuncSetAttribute(mlp_kernel<HID>,  cudaFuncAttributeMaxDynamicSharedMemorySize, smemMlp);

    const int mlpBlocks = (N_NODES + 127) / 128;
    const int applyN4   = N_NODES * HID / 4;

    // ---- layer 0 (CIN=64): AGG = x; AGG += scatter(x) ----
    {
        int n4 = N_NODES * IN_C / 4;
        copy4_kernel<<<(n4 + 255) / 256, 256>>>((float4*)AGG, (const float4*)x, n4);
        long long sthreads = (long long)N_EDGES * (IN_C / 4);
        scatter_kernel<IN_C><<<(int)((sthreads + 255) / 256), 256>>>(ei, x, AGG);
        zero_kernel<<<1, 256>>>(STATS, 2 * HID);
        mlp_kernel<IN_C><<<mlpBlocks, 256, smemMlp>>>(AGG, L[0][0], L[0][1], L[0][2], L[0][3], Z, STATS);
        bn_finalize_kernel<<<1, HID>>>(L[0][4], L[0][5], STATS, SCALE, SHIFT);
        bn_apply_kernel<<<(applyN4 + 255) / 256, 256>>>((const float4*)Z, (float4*)H, (float4*)AGG, 1, SCALE, SHIFT);
    }

    // ---- layers 1,2 (CIN=128) ----
    for (int l = 1; l < 3; l++) {
        long long sthreads = (long long)N_EDGES * (HID / 4);
        scatter_kernel<HID><<<(int)((sthreads + 255) / 256), 256>>>(ei, H, AGG);
        zero_kernel<<<1, 256>>>(STATS, 2 * HID);
        mlp_kernel<HID><<<mlpBlocks, 256, smemMlp>>>(AGG, L[l][0], L[l][1], L[l][2], L[l][3], Z, STATS);
        bn_finalize_kernel<<<1, HID>>>(L[l][4], L[l][5], STATS, SCALE, SHIFT);
        int writeAgg = (l < 2) ? 1 : 0;
        bn_apply_kernel<<<(applyN4 + 255) / 256, 256>>>((const float4*)Z, (float4*)H, (float4*)AGG, writeAgg, SCALE, SHIFT);
    }

    // ---- pool + projection ----
    zero_kernel<<<(N_GRAPHS * HID + 255) / 256, 256>>>(POOL, N_GRAPHS * HID);
    pool_kernel<<<(N_NODES + 255) / 256, 128>>>(H, batch, POOL);
    count_kernel<<<1, N_GRAPHS>>>(batch, CINV);
    proj_kernel<<<N_GRAPHS, HID>>>(proj_w, proj_b, POOL, CINV, out);
}